// round 4
// baseline (speedup 1.0000x reference)
#include <cuda_runtime.h>
#include <cstdint>
#include <cstddef>

// Problem dims (fixed)
#define BB   32
#define SS   2048
#define DD   256
#define HH   512
#define GG   2048   // 4*H
#define OO   256

// ---------------- scratch (device globals: allocation-free) ----------------
__device__ float g_xg[(size_t)BB * SS * GG];   // 512 MB: x@Wx + b
__device__ float g_hst[(size_t)BB * SS * HH];  // 128 MB: stacked h
__device__ float g_h[BB * HH];                 // current h
__device__ unsigned g_cnt[4];                  // per-batch-group barrier counters
__device__ unsigned g_gen[4];                  // per-batch-group barrier generations

// ---------------- f32x2 helpers ----------------
__device__ __forceinline__ unsigned long long ffma2(unsigned long long a,
                                                    unsigned long long b,
                                                    unsigned long long c) {
    unsigned long long d;
    asm("fma.rn.f32x2 %0, %1, %2, %3;" : "=l"(d) : "l"(a), "l"(b), "l"(c));
    return d;
}
__device__ __forceinline__ unsigned long long splat2(float x) {
    unsigned long long d; unsigned xi = __float_as_uint(x);
    asm("mov.b64 %0, {%1, %2};" : "=l"(d) : "r"(xi), "r"(xi));
    return d;
}
__device__ __forceinline__ unsigned long long pack2(float lo, float hi) {
    unsigned long long d;
    asm("mov.b64 %0, {%1, %2};" : "=l"(d) : "r"(__float_as_uint(lo)), "r"(__float_as_uint(hi)));
    return d;
}
__device__ __forceinline__ float lo2(unsigned long long v) { return __uint_as_float((unsigned)v); }
__device__ __forceinline__ float hi2(unsigned long long v) { return __uint_as_float((unsigned)(v >> 32)); }

__device__ __forceinline__ float fsigmoid(float x) { return 1.f / (1.f + __expf(-x)); }
__device__ __forceinline__ float ftanh(float x) { float e = __expf(2.f * x); return 1.f - 2.f / (e + 1.f); }

// ---------------- scoped barrier: 32 CTAs of one batch-group ----------------
__device__ __forceinline__ void gsync(int grp) {
    __threadfence();          // release this CTA's global writes
    __syncthreads();
    if (threadIdx.x == 0) {
        volatile unsigned* genp = (volatile unsigned*)&g_gen[grp];
        unsigned my = *genp;
        __threadfence();
        unsigned arr = atomicAdd(&g_cnt[grp], 1u);
        if (arr == 31u) {
            atomicExch(&g_cnt[grp], 0u);
            __threadfence();
            *genp = my + 1u;  // release
        } else {
            while (*genp == my) { __nanosleep(64); }
        }
        __threadfence();      // acquire
    }
    __syncthreads();
}

// ---------------- generic fp32 GEMM: C[M,N] = A[M,K] @ B[K,N] + bias[N] ----------------
// BM=128, BN=128, BK=8, 256 threads, 8x8 per thread via f32x2 (n-paired accumulators).
__global__ __launch_bounds__(256, 2)
void gemm_f32(const float* __restrict__ A, const float* __restrict__ Bm,
              const float* __restrict__ bias, float* __restrict__ C,
              int M, int N, int K) {
    __shared__ float As[8][136];   // [k][m], padded
    __shared__ float Bs[8][136];   // [k][n]

    const int tid = threadIdx.x;
    const int tx = tid & 15;        // n-tile 0..15
    const int ty = tid >> 4;        // m-tile 0..15
    const int mBase = blockIdx.y * 128;
    const int nBase = blockIdx.x * 128;

    // loaders
    const int lr = tid >> 1;          // A row 0..127
    const int lk = (tid & 1) * 4;     // A k offset 0/4
    const int bk = tid >> 5;          // B k row 0..7
    const int bc = (tid & 31) * 4;    // B col 0..124

    unsigned long long acc[8][4];
#pragma unroll
    for (int i = 0; i < 8; i++)
#pragma unroll
        for (int j = 0; j < 4; j++) acc[i][j] = 0ull;

    // prefetch first tile
    float4 a4 = *(const float4*)&A[(size_t)(mBase + lr) * K + lk];
    float4 b4 = *(const float4*)&Bm[(size_t)bk * N + nBase + bc];

    for (int k0 = 0; k0 < K; k0 += 8) {
        As[lk + 0][lr] = a4.x; As[lk + 1][lr] = a4.y;
        As[lk + 2][lr] = a4.z; As[lk + 3][lr] = a4.w;
        *(float4*)&Bs[bk][bc] = b4;
        __syncthreads();

        if (k0 + 8 < K) {
            a4 = *(const float4*)&A[(size_t)(mBase + lr) * K + (k0 + 8) + lk];
            b4 = *(const float4*)&Bm[(size_t)(k0 + 8 + bk) * N + nBase + bc];
        }

#pragma unroll
        for (int kk = 0; kk < 8; kk++) {
            float4 am0 = *(const float4*)&As[kk][ty * 8];
            float4 am1 = *(const float4*)&As[kk][ty * 8 + 4];
            ulonglong2 bn0 = *(const ulonglong2*)&Bs[kk][tx * 8];
            ulonglong2 bn1 = *(const ulonglong2*)&Bs[kk][tx * 8 + 4];
            float am[8] = {am0.x, am0.y, am0.z, am0.w, am1.x, am1.y, am1.z, am1.w};
#pragma unroll
            for (int i = 0; i < 8; i++) {
                unsigned long long as2 = splat2(am[i]);
                acc[i][0] = ffma2(as2, bn0.x, acc[i][0]);
                acc[i][1] = ffma2(as2, bn0.y, acc[i][1]);
                acc[i][2] = ffma2(as2, bn1.x, acc[i][2]);
                acc[i][3] = ffma2(as2, bn1.y, acc[i][3]);
            }
        }
        __syncthreads();
    }

    // epilogue: add bias, store 8x8
    float bs[8];
#pragma unroll
    for (int j = 0; j < 8; j++) bs[j] = bias[nBase + tx * 8 + j];

#pragma unroll
    for (int i = 0; i < 8; i++) {
        int row = mBase + ty * 8 + i;
        float r0 = lo2(acc[i][0]) + bs[0];
        float r1 = hi2(acc[i][0]) + bs[1];
        float r2 = lo2(acc[i][1]) + bs[2];
        float r3 = hi2(acc[i][1]) + bs[3];
        float r4 = lo2(acc[i][2]) + bs[4];
        float r5 = hi2(acc[i][2]) + bs[5];
        float r6 = lo2(acc[i][3]) + bs[6];
        float r7 = hi2(acc[i][3]) + bs[7];
        float4 v0 = make_float4(r0, r1, r2, r3);
        float4 v1 = make_float4(r4, r5, r6, r7);
        *(float4*)&C[(size_t)row * N + nBase + tx * 8] = v0;
        *(float4*)&C[(size_t)row * N + nBase + tx * 8 + 4] = v1;
    }
}

// ---------------- persistent LSTM recurrence ----------------
// 128 CTAs x 256 threads. CTA = (j-tile of 16, batch-group of 8).
// Each CTA owns gate columns {g*512 + j0 + jj} for its 16-wide j-range (all 4
// gates), so the c/h pointwise update is CTA-local. Per-thread: one column,
// one 128-wide k-chunk, ALL Wh weights held in registers (64 f32x2 pairs,
// loaded once for the whole sequence). k-partials reduced through SMEM.
// One scoped barrier per timestep among the 32 CTAs of a batch-group.
__global__ __launch_bounds__(256, 1)
void lstm_kernel(const float* __restrict__ Wh,   // [512][2048]
                 const float* __restrict__ xg,   // [B][S][2048] (x@Wx + b)
                 float* __restrict__ hst) {      // [B][S][512]
    __shared__ float hs[8][512];        // [b][k] current h of the 8 batches
    __shared__ float parts[4][64][8];   // [kc][r][b] partial dot sums
    __shared__ float gbuf[64][8];       // [r][b] gate pre-activations
    __shared__ float csm[16][8];        // [jj][b] cell state (persistent)

    const int tid = threadIdx.x;
    const int bid = blockIdx.x;
    const int bg = bid & 3;        // batch group 0..3 (8 batches each)
    const int jt = bid >> 2;       // j-tile 0..31
    const int j0 = jt << 4;

    const int kc = tid >> 6;       // k-chunk 0..3 (128 k each)
    const int r  = tid & 63;       // 0..63 column-slot within CTA
    const int gate = r >> 4;       // 0..3
    const int jj = r & 15;
    const int col = gate * 512 + j0 + jj;

    // ---- load this thread's Wh column chunk into registers (once) ----
    unsigned long long w01[32], w23[32];
    {
        const float* wp = Wh + (size_t)(kc * 128) * GG + col;
#pragma unroll
        for (int i = 0; i < 32; i++) {
            float a0 = wp[0];
            float a1 = wp[GG];
            float a2 = wp[2 * GG];
            float a3 = wp[3 * GG];
            wp += 4 * GG;
            w01[i] = pack2(a0, a1);
            w23[i] = pack2(a2, a3);
        }
    }

    // xg prefetch pointers: reduce slot rr == this thread's r, so column == col.
    const int bb0 = tid >> 6;      // 0..3
    const float* xgp0 = xg + (size_t)(bg * 8 + bb0) * SS * GG + col;
    const float* xgp1 = xg + (size_t)(bg * 8 + bb0 + 4) * SS * GG + col;

    // ---- init: zero h for this batch group (one CTA per group), zero c ----
    if (jt == 0) {
        for (int i = tid; i < 8 * HH; i += 256) g_h[bg * 8 * HH + i] = 0.f;
    }
    if (tid < 128) csm[tid & 15][tid >> 4] = 0.f;
    gsync(bg);

    for (int t = 0; t < SS; t++) {
        // prefetch this thread's two xg gate values for step t (used post-reduce)
        float xga = xgp0[(size_t)t * GG];
        float xgb = xgp1[(size_t)t * GG];

        // stage h[8][512] into SMEM (coalesced float4)
        {
            const float4* hb4 = (const float4*)(g_h + bg * 8 * HH);
#pragma unroll
            for (int rr = 0; rr < 4; rr++) {
                int idx = tid + 256 * rr;   // 0..1023
                int b = idx >> 7;           // 0..7
                int k4 = idx & 127;
                float4 v = hb4[b * 128 + k4];
                *(float4*)&hs[b][k4 * 4] = v;
            }
        }
        __syncthreads();

        // ---- partial dot products from register-resident weights ----
        unsigned long long acc[8];
#pragma unroll
        for (int b = 0; b < 8; b++) acc[b] = 0ull;

#pragma unroll
        for (int i = 0; i < 32; i++) {
            const int kk = kc * 128 + i * 4;
#pragma unroll
            for (int b = 0; b < 8; b++) {
                ulonglong2 hv = *(const ulonglong2*)&hs[b][kk];
                acc[b] = ffma2(w01[i], hv.x, acc[b]);
                acc[b] = ffma2(w23[i], hv.y, acc[b]);
            }
        }

        // write partials to SMEM
        {
            float4 p0, p1;
            p0.x = lo2(acc[0]) + hi2(acc[0]);
            p0.y = lo2(acc[1]) + hi2(acc[1]);
            p0.z = lo2(acc[2]) + hi2(acc[2]);
            p0.w = lo2(acc[3]) + hi2(acc[3]);
            p1.x = lo2(acc[4]) + hi2(acc[4]);
            p1.y = lo2(acc[5]) + hi2(acc[5]);
            p1.z = lo2(acc[6]) + hi2(acc[6]);
            p1.w = lo2(acc[7]) + hi2(acc[7]);
            *(float4*)&parts[kc][r][0] = p0;
            *(float4*)&parts[kc][r][4] = p1;
        }
        __syncthreads();

        // ---- reduce k-chunks + add xg -> gate pre-activations ----
        {
            float s0 = parts[0][r][bb0] + parts[1][r][bb0]
                     + parts[2][r][bb0] + parts[3][r][bb0] + xga;
            float s1 = parts[0][r][bb0 + 4] + parts[1][r][bb0 + 4]
                     + parts[2][r][bb0 + 4] + parts[3][r][bb0 + 4] + xgb;
            gbuf[r][bb0] = s0;
            gbuf[r][bb0 + 4] = s1;
        }
        __syncthreads();

        // ---- pointwise LSTM cell update (CTA-local) ----
        if (tid < 128) {
            int jjx = tid & 15;
            int bb = tid >> 4;              // 0..7
            float vi = gbuf[0 * 16 + jjx][bb];
            float vf = gbuf[1 * 16 + jjx][bb];
            float vg = gbuf[2 * 16 + jjx][bb];
            float vo = gbuf[3 * 16 + jjx][bb];
            float si = fsigmoid(vi);
            float sf = fsigmoid(vf);
            float so = fsigmoid(vo);
            float tg = ftanh(vg);
            float c = sf * csm[jjx][bb] + si * tg;
            float h = so * ftanh(c);
            csm[jjx][bb] = c;
            int bglob = bg * 8 + bb;
            g_h[bglob * HH + j0 + jjx] = h;
            hst[((size_t)bglob * SS + t) * HH + j0 + jjx] = h;
        }

        gsync(bg);  // h for this batch-group fully updated before next step
    }
}

// ---------------- launch ----------------
extern "C" void kernel_launch(void* const* d_in, const int* in_sizes, int n_in,
                              void* d_out, int out_size) {
    const float* x  = (const float*)d_in[0];
    const float* Wx = (const float*)d_in[1];
    const float* Wh = (const float*)d_in[2];
    const float* b  = (const float*)d_in[3];
    const float* Wo = (const float*)d_in[4];
    const float* bo = (const float*)d_in[5];
    float* out = (float*)d_out;

    float *xg_p, *hst_p;
    cudaGetSymbolAddress((void**)&xg_p, g_xg);
    cudaGetSymbolAddress((void**)&hst_p, g_hst);

    // xg = x @ Wx + b   : M=65536, N=2048, K=256
    gemm_f32<<<dim3(GG / 128, (BB * SS) / 128), 256>>>(x, Wx, b, xg_p,
                                                       BB * SS, GG, DD);
    // recurrence
    lstm_kernel<<<128, 256>>>(Wh, xg_p, hst_p);
    // y = h_stacked @ Wo + bo : M=65536, N=256, K=512
    gemm_f32<<<dim3(OO / 128, (BB * SS) / 128), 256>>>(hst_p, Wo, bo, out,
                                                       BB * SS, OO, HH);
}

// round 7
// speedup vs baseline: 1.1673x; 1.1673x over previous
#include <cuda_runtime.h>
#include <cstdint>
#include <cstddef>

// Problem dims (fixed)
#define BB   32
#define SS   2048
#define DD   256
#define HH   512
#define GG   2048   // 4*H
#define OO   256
#define NG   8      // batch groups
#define GB   4      // batches per group

// ---------------- scratch (device globals: allocation-free) ----------------
__device__ float g_xg[(size_t)BB * SS * GG];   // 512 MB: x@Wx + b
__device__ float g_hst[(size_t)BB * SS * HH];  // 128 MB: stacked h
__device__ float g_hbuf[2][BB * HH];           // ping-pong h state
__device__ unsigned g_arr[NG];                 // monotonic per-group arrival counters

// ---------------- f32x2 helpers ----------------
__device__ __forceinline__ unsigned long long ffma2(unsigned long long a,
                                                    unsigned long long b,
                                                    unsigned long long c) {
    unsigned long long d;
    asm("fma.rn.f32x2 %0, %1, %2, %3;" : "=l"(d) : "l"(a), "l"(b), "l"(c));
    return d;
}
__device__ __forceinline__ unsigned long long splat2(float x) {
    unsigned long long d; unsigned xi = __float_as_uint(x);
    asm("mov.b64 %0, {%1, %2};" : "=l"(d) : "r"(xi), "r"(xi));
    return d;
}
__device__ __forceinline__ unsigned long long pack2(float lo, float hi) {
    unsigned long long d;
    asm("mov.b64 %0, {%1, %2};" : "=l"(d) : "r"(__float_as_uint(lo)), "r"(__float_as_uint(hi)));
    return d;
}
__device__ __forceinline__ float lo2(unsigned long long v) { return __uint_as_float((unsigned)v); }
__device__ __forceinline__ float hi2(unsigned long long v) { return __uint_as_float((unsigned)(v >> 32)); }

__device__ __forceinline__ float fsigmoid(float x) { return 1.f / (1.f + __expf(-x)); }
__device__ __forceinline__ float ftanh(float x) { float e = __expf(2.f * x); return 1.f - 2.f / (e + 1.f); }

// ---------------- release/acquire barrier primitives ----------------
__device__ __forceinline__ void arrive_rel(unsigned* p) {
    unsigned old;
    asm volatile("atom.release.gpu.global.add.u32 %0, [%1], 1;"
                 : "=r"(old) : "l"(p) : "memory");
}
__device__ __forceinline__ unsigned ld_acq(const unsigned* p) {
    unsigned v;
    asm volatile("ld.acquire.gpu.global.u32 %0, [%1];" : "=r"(v) : "l"(p) : "memory");
    return v;
}
__device__ __forceinline__ void poll_ge(unsigned* p, unsigned need) {
    int tries = 0;
    while (ld_acq(p) < need) {
        if (++tries > 2) __nanosleep(40);
    }
}

// ---------------- fp32 GEMM, double-buffered SMEM (1 sync / k-tile) ----------------
// C[M,N] = A[M,K] @ B[K,N] + bias[N]; BM=BN=128, BK=8, 256 thr, 8x8/thread f32x2.
__global__ __launch_bounds__(256, 2)
void gemm_f32(const float* __restrict__ A, const float* __restrict__ Bm,
              const float* __restrict__ bias, float* __restrict__ C,
              int M, int N, int K) {
    __shared__ float As[2][8][136];
    __shared__ float Bs[2][8][136];

    const int tid = threadIdx.x;
    const int tx = tid & 15;
    const int ty = tid >> 4;
    const int mBase = blockIdx.y * 128;
    const int nBase = blockIdx.x * 128;

    const int lr = tid >> 1;          // A row 0..127
    const int lk = (tid & 1) * 4;     // A k offset 0/4
    const int bk = tid >> 5;          // B k row 0..7
    const int bc = (tid & 31) * 4;    // B col 0..124

    unsigned long long acc[8][4];
#pragma unroll
    for (int i = 0; i < 8; i++)
#pragma unroll
        for (int j = 0; j < 4; j++) acc[i][j] = 0ull;

    float4 a4 = *(const float4*)&A[(size_t)(mBase + lr) * K + lk];
    float4 b4 = *(const float4*)&Bm[(size_t)bk * N + nBase + bc];

    int cur = 0;
    for (int k0 = 0; k0 < K; k0 += 8) {
        // stage current tile
        As[cur][lk + 0][lr] = a4.x; As[cur][lk + 1][lr] = a4.y;
        As[cur][lk + 2][lr] = a4.z; As[cur][lk + 3][lr] = a4.w;
        *(float4*)&Bs[cur][bk][bc] = b4;
        __syncthreads();            // single sync: tile 'cur' fully staged

        if (k0 + 8 < K) {           // prefetch next tile (overlaps compute)
            a4 = *(const float4*)&A[(size_t)(mBase + lr) * K + (k0 + 8) + lk];
            b4 = *(const float4*)&Bm[(size_t)(k0 + 8 + bk) * N + nBase + bc];
        }

#pragma unroll
        for (int kk = 0; kk < 8; kk++) {
            float4 am0 = *(const float4*)&As[cur][kk][ty * 8];
            float4 am1 = *(const float4*)&As[cur][kk][ty * 8 + 4];
            ulonglong2 bn0 = *(const ulonglong2*)&Bs[cur][kk][tx * 8];
            ulonglong2 bn1 = *(const ulonglong2*)&Bs[cur][kk][tx * 8 + 4];
            float am[8] = {am0.x, am0.y, am0.z, am0.w, am1.x, am1.y, am1.z, am1.w};
#pragma unroll
            for (int i = 0; i < 8; i++) {
                unsigned long long as2 = splat2(am[i]);
                acc[i][0] = ffma2(as2, bn0.x, acc[i][0]);
                acc[i][1] = ffma2(as2, bn0.y, acc[i][1]);
                acc[i][2] = ffma2(as2, bn1.x, acc[i][2]);
                acc[i][3] = ffma2(as2, bn1.y, acc[i][3]);
            }
        }
        cur ^= 1;   // next store goes to the other buffer; WAR-safe via the
                    // sync of the NEXT iteration (gates reuse 2 tiles later)
    }

    float bs[8];
#pragma unroll
    for (int j = 0; j < 8; j++) bs[j] = bias[nBase + tx * 8 + j];

#pragma unroll
    for (int i = 0; i < 8; i++) {
        int row = mBase + ty * 8 + i;
        float4 v0 = make_float4(lo2(acc[i][0]) + bs[0], hi2(acc[i][0]) + bs[1],
                                lo2(acc[i][1]) + bs[2], hi2(acc[i][1]) + bs[3]);
        float4 v1 = make_float4(lo2(acc[i][2]) + bs[4], hi2(acc[i][2]) + bs[5],
                                lo2(acc[i][3]) + bs[6], hi2(acc[i][3]) + bs[7]);
        *(float4*)&C[(size_t)row * N + nBase + tx * 8] = v0;
        *(float4*)&C[(size_t)row * N + nBase + tx * 8 + 4] = v1;
    }
}

// ---------------- persistent LSTM recurrence, dual-group pipelined ----------------
// 128 CTAs x 256 threads. CTA (bid) = j-tile (bid>>2, 16 cols) x group pair
// (gA=bid&3, gB=gA+4). 8 groups of 4 batches; 32 CTAs per group barrier.
// Wh slice register-resident, SHARED between the CTA's two groups. Per step the
// two groups are processed back-to-back, so each group's inter-CTA barrier is
// hidden under the other group's compute. Monotonic release/acquire counters +
// ping-pong h buffer (no reset per step, no membar, race-free by construction).
__global__ __launch_bounds__(256, 1)
void lstm_kernel(const float* __restrict__ Wh,   // [512][2048]
                 const float* __restrict__ xg,   // [B][S][2048]
                 float* __restrict__ hst) {      // [B][S][512]
    __shared__ float hsA[GB][512];
    __shared__ float hsB[GB][512];
    __shared__ float parts[4][64][GB];   // reused A/B (sync-separated)
    __shared__ float gbufA[64][GB];
    __shared__ float gbufB[64][GB];
    __shared__ float csm[2][16][GB];     // persistent cell state per group

    const int tid = threadIdx.x;
    const int bid = blockIdx.x;
    const int gA = bid & 3;
    const int gB = gA + 4;
    const int jt = bid >> 2;       // 0..31
    const int j0 = jt << 4;

    const int kc = tid >> 6;       // k-chunk 0..3 (also batch index for reduce)
    const int r  = tid & 63;
    const int gate = r >> 4;
    const int jj = r & 15;
    const int col = gate * 512 + j0 + jj;

    // ---- Wh slice into registers (once, shared by both groups) ----
    unsigned long long w01[32], w23[32];
    {
        const float* wp = Wh + (size_t)(kc * 128) * GG + col;
#pragma unroll
        for (int i = 0; i < 32; i++) {
            float a0 = wp[0];
            float a1 = wp[GG];
            float a2 = wp[2 * GG];
            float a3 = wp[3 * GG];
            wp += 4 * GG;
            w01[i] = pack2(a0, a1);
            w23[i] = pack2(a2, a3);
        }
    }

    // xg pointers: reduce-thread (r == this r, batch == kc)
    const float* xgpA = xg + ((size_t)(gA * GB + kc) * SS) * GG + col;
    const float* xgpB = xg + ((size_t)(gB * GB + kc) * SS) * GG + col;

    // ---- init: zero own slice of ping buffer 0, zero cell state ----
    if (tid < 64) {
        int bb = tid >> 4, jx = tid & 15;
        g_hbuf[0][(gA * GB + bb) * HH + j0 + jx] = 0.f;
        g_hbuf[0][(gB * GB + bb) * HH + j0 + jx] = 0.f;
    }
    if (tid < 128) {
        int pg = tid >> 6, x = tid & 63;
        csm[pg][x & 15][x >> 4] = 0.f;
    }
    __syncthreads();
    if (tid == 0) { arrive_rel(&g_arr[gA]); arrive_rel(&g_arr[gB]); }

    for (int t = 0; t < SS; t++) {
        const unsigned need = 32u * (unsigned)(t + 1);
        const int pin = t & 1, pout = pin ^ 1;

        // ---- wait A ready, load A h-state ----
        if (tid == 0) poll_ge(&g_arr[gA], need);
        __syncthreads();   // broadcast acquire
        const float4* bufA4 = (const float4*)(g_hbuf[pin] + gA * GB * HH);
        float4 a0 = bufA4[tid];
        float4 a1 = bufA4[tid + 256];
        // xg prefetch for both groups (DRAM latency hidden under dots)
        float xgA = xgpA[(size_t)t * GG];
        float xgB = xgpB[(size_t)t * GG];

        {
            int b0i = tid >> 7, k0i = tid & 127;
            *(float4*)&hsA[b0i][k0i * 4] = a0;
            int b1i = (tid + 256) >> 7, k1i = (tid + 256) & 127;
            *(float4*)&hsA[b1i][k1i * 4] = a1;
        }
        __syncthreads();

        // ---- dot A ----
        unsigned long long acc[GB];
#pragma unroll
        for (int b = 0; b < GB; b++) acc[b] = 0ull;
#pragma unroll
        for (int i = 0; i < 32; i++) {
            const int kk = kc * 128 + i * 4;
#pragma unroll
            for (int b = 0; b < GB; b++) {
                ulonglong2 hv = *(const ulonglong2*)&hsA[b][kk];
                acc[b] = ffma2(w01[i], hv.x, acc[b]);
                acc[b] = ffma2(w23[i], hv.y, acc[b]);
            }
        }
        {
            float4 p;
            p.x = lo2(acc[0]) + hi2(acc[0]);
            p.y = lo2(acc[1]) + hi2(acc[1]);
            p.z = lo2(acc[2]) + hi2(acc[2]);
            p.w = lo2(acc[3]) + hi2(acc[3]);
            *(float4*)&parts[kc][r][0] = p;
        }
        // overlap: tid0 confirms B barrier while others drain to the bar
        if (tid == 0) poll_ge(&g_arr[gB], need);
        __syncthreads();

        // B h-state loads (latency overlaps reduceA/pointwiseA)
        const float4* bufB4 = (const float4*)(g_hbuf[pin] + gB * GB * HH);
        float4 b0 = bufB4[tid];
        float4 b1 = bufB4[tid + 256];

        // ---- reduce A + xg ----
        gbufA[r][kc] = parts[0][r][kc] + parts[1][r][kc]
                     + parts[2][r][kc] + parts[3][r][kc] + xgA;
        __syncthreads();

        // ---- pointwise A ----
        if (tid < 64) {
            int bb = tid >> 4, jx = tid & 15;
            float vi = gbufA[0 * 16 + jx][bb];
            float vf = gbufA[1 * 16 + jx][bb];
            float vg = gbufA[2 * 16 + jx][bb];
            float vo = gbufA[3 * 16 + jx][bb];
            float c = fsigmoid(vf) * csm[0][jx][bb] + fsigmoid(vi) * ftanh(vg);
            float h = fsigmoid(vo) * ftanh(c);
            csm[0][jx][bb] = c;
            int bglob = gA * GB + bb;
            g_hbuf[pout][bglob * HH + j0 + jx] = h;
            hst[((size_t)bglob * SS + t) * HH + j0 + jx] = h;
        }
        // stage B h-state (hsB free: previous dotB fully consumed it)
        {
            int b0i = tid >> 7, k0i = tid & 127;
            *(float4*)&hsB[b0i][k0i * 4] = b0;
            int b1i = (tid + 256) >> 7, k1i = (tid + 256) & 127;
            *(float4*)&hsB[b1i][k1i * 4] = b1;
        }
        __syncthreads();
        if (tid == 0) arrive_rel(&g_arr[gA]);   // h(t+1) of A published

        // ---- dot B ----
#pragma unroll
        for (int b = 0; b < GB; b++) acc[b] = 0ull;
#pragma unroll
        for (int i = 0; i < 32; i++) {
            const int kk = kc * 128 + i * 4;
#pragma unroll
            for (int b = 0; b < GB; b++) {
                ulonglong2 hv = *(const ulonglong2*)&hsB[b][kk];
                acc[b] = ffma2(w01[i], hv.x, acc[b]);
                acc[b] = ffma2(w23[i], hv.y, acc[b]);
            }
        }
        {
            float4 p;
            p.x = lo2(acc[0]) + hi2(acc[0]);
            p.y = lo2(acc[1]) + hi2(acc[1]);
            p.z = lo2(acc[2]) + hi2(acc[2]);
            p.w = lo2(acc[3]) + hi2(acc[3]);
            *(float4*)&parts[kc][r][0] = p;
        }
        __syncthreads();

        // ---- reduce B + xg ----
        gbufB[r][kc] = parts[0][r][kc] + parts[1][r][kc]
                     + parts[2][r][kc] + parts[3][r][kc] + xgB;
        __syncthreads();

        // ---- pointwise B ----
        if (tid < 64) {
            int bb = tid >> 4, jx = tid & 15;
            float vi = gbufB[0 * 16 + jx][bb];
            float vf = gbufB[1 * 16 + jx][bb];
            float vg = gbufB[2 * 16 + jx][bb];
            float vo = gbufB[3 * 16 + jx][bb];
            float c = fsigmoid(vf) * csm[1][jx][bb] + fsigmoid(vi) * ftanh(vg);
            float h = fsigmoid(vo) * ftanh(c);
            csm[1][jx][bb] = c;
            int bglob = gB * GB + bb;
            g_hbuf[pout][bglob * HH + j0 + jx] = h;
            hst[((size_t)bglob * SS + t) * HH + j0 + jx] = h;
        }
        __syncthreads();
        if (tid == 0) arrive_rel(&g_arr[gB]);   // h(t+1) of B published
    }

    // ---- reset counters for graph replay (after all arrives are in) ----
    if (bid < 4 && tid == 0) {
        const unsigned total = 32u * (unsigned)(SS + 1);
        poll_ge(&g_arr[gA], total);
        poll_ge(&g_arr[gB], total);
        // all participants have posted their final arrive; nobody reads anymore
        asm volatile("st.relaxed.gpu.global.u32 [%0], %1;" :: "l"(&g_arr[gA]), "r"(0u) : "memory");
        asm volatile("st.relaxed.gpu.global.u32 [%0], %1;" :: "l"(&g_arr[gB]), "r"(0u) : "memory");
    }
}

// ---------------- launch ----------------
extern "C" void kernel_launch(void* const* d_in, const int* in_sizes, int n_in,
                              void* d_out, int out_size) {
    const float* x  = (const float*)d_in[0];
    const float* Wx = (const float*)d_in[1];
    const float* Wh = (const float*)d_in[2];
    const float* b  = (const float*)d_in[3];
    const float* Wo = (const float*)d_in[4];
    const float* bo = (const float*)d_in[5];
    float* out = (float*)d_out;

    float *xg_p, *hst_p;
    cudaGetSymbolAddress((void**)&xg_p, g_xg);
    cudaGetSymbolAddress((void**)&hst_p, g_hst);

    // xg = x @ Wx + b   : M=65536, N=2048, K=256
    gemm_f32<<<dim3(GG / 128, (BB * SS) / 128), 256>>>(x, Wx, b, xg_p,
                                                       BB * SS, GG, DD);
    // recurrence
    lstm_kernel<<<128, 256>>>(Wh, xg_p, hst_p);
    // y = h_stacked @ Wo + bo : M=65536, N=256, K=512
    gemm_f32<<<dim3(OO / 128, (BB * SS) / 128), 256>>>(hst_p, Wo, bo, out,
                                                       BB * SS, OO, HH);
}

// round 10
// speedup vs baseline: 1.1864x; 1.0164x over previous
#include <cuda_runtime.h>
#include <cstdint>
#include <cstddef>

// Problem dims (fixed)
#define BB   32
#define SS   2048
#define DD   256
#define HH   512
#define GG   2048   // 4*H
#define OO   256
#define NG   8      // batch groups
#define GB   4      // batches per group

// ---------------- scratch (device globals: allocation-free) ----------------
__device__ float g_xg[(size_t)BB * SS * GG];   // 512 MB: x@Wx + b
__device__ float g_hst[(size_t)BB * SS * HH];  // 128 MB: stacked h
__device__ float g_hbuf[2][BB * HH];           // ping-pong h state
__device__ unsigned g_arr[NG];                 // monotonic per-group arrival counters

// ---------------- f32x2 helpers ----------------
__device__ __forceinline__ unsigned long long ffma2(unsigned long long a,
                                                    unsigned long long b,
                                                    unsigned long long c) {
    unsigned long long d;
    asm("fma.rn.f32x2 %0, %1, %2, %3;" : "=l"(d) : "l"(a), "l"(b), "l"(c));
    return d;
}
__device__ __forceinline__ unsigned long long splat2(float x) {
    unsigned long long d; unsigned xi = __float_as_uint(x);
    asm("mov.b64 %0, {%1, %2};" : "=l"(d) : "r"(xi), "r"(xi));
    return d;
}
__device__ __forceinline__ unsigned long long pack2(float lo, float hi) {
    unsigned long long d;
    asm("mov.b64 %0, {%1, %2};" : "=l"(d) : "r"(__float_as_uint(lo)), "r"(__float_as_uint(hi)));
    return d;
}
__device__ __forceinline__ float lo2(unsigned long long v) { return __uint_as_float((unsigned)v); }
__device__ __forceinline__ float hi2(unsigned long long v) { return __uint_as_float((unsigned)(v >> 32)); }

__device__ __forceinline__ float fsigmoid(float x) { return 1.f / (1.f + __expf(-x)); }
__device__ __forceinline__ float ftanh(float x) { float e = __expf(2.f * x); return 1.f - 2.f / (e + 1.f); }

// ---------------- release/acquire barrier primitives ----------------
__device__ __forceinline__ void arrive_rel(unsigned* p) {
    unsigned old;
    asm volatile("atom.release.gpu.global.add.u32 %0, [%1], 1;"
                 : "=r"(old) : "l"(p) : "memory");
}
__device__ __forceinline__ unsigned ld_acq(const unsigned* p) {
    unsigned v;
    asm volatile("ld.acquire.gpu.global.u32 %0, [%1];" : "=r"(v) : "l"(p) : "memory");
    return v;
}
__device__ __forceinline__ void poll_ge(unsigned* p, unsigned need) {
    int tries = 0;
    while (ld_acq(p) < need) {
        if (++tries > 64) __nanosleep(32);   // L2 RT is the natural poll period
    }
}

// ---------------- fp32 GEMM, double-buffered SMEM (1 sync / k-tile) ----------------
__global__ __launch_bounds__(256, 2)
void gemm_f32(const float* __restrict__ A, const float* __restrict__ Bm,
              const float* __restrict__ bias, float* __restrict__ C,
              int M, int N, int K) {
    __shared__ float As[2][8][136];
    __shared__ float Bs[2][8][136];

    const int tid = threadIdx.x;
    const int tx = tid & 15;
    const int ty = tid >> 4;
    const int mBase = blockIdx.y * 128;
    const int nBase = blockIdx.x * 128;

    const int lr = tid >> 1;
    const int lk = (tid & 1) * 4;
    const int bk = tid >> 5;
    const int bc = (tid & 31) * 4;

    unsigned long long acc[8][4];
#pragma unroll
    for (int i = 0; i < 8; i++)
#pragma unroll
        for (int j = 0; j < 4; j++) acc[i][j] = 0ull;

    float4 a4 = *(const float4*)&A[(size_t)(mBase + lr) * K + lk];
    float4 b4 = *(const float4*)&Bm[(size_t)bk * N + nBase + bc];

    int cur = 0;
    for (int k0 = 0; k0 < K; k0 += 8) {
        As[cur][lk + 0][lr] = a4.x; As[cur][lk + 1][lr] = a4.y;
        As[cur][lk + 2][lr] = a4.z; As[cur][lk + 3][lr] = a4.w;
        *(float4*)&Bs[cur][bk][bc] = b4;
        __syncthreads();

        if (k0 + 8 < K) {
            a4 = *(const float4*)&A[(size_t)(mBase + lr) * K + (k0 + 8) + lk];
            b4 = *(const float4*)&Bm[(size_t)(k0 + 8 + bk) * N + nBase + bc];
        }

#pragma unroll
        for (int kk = 0; kk < 8; kk++) {
            float4 am0 = *(const float4*)&As[cur][kk][ty * 8];
            float4 am1 = *(const float4*)&As[cur][kk][ty * 8 + 4];
            ulonglong2 bn0 = *(const ulonglong2*)&Bs[cur][kk][tx * 8];
            ulonglong2 bn1 = *(const ulonglong2*)&Bs[cur][kk][tx * 8 + 4];
            float am[8] = {am0.x, am0.y, am0.z, am0.w, am1.x, am1.y, am1.z, am1.w};
#pragma unroll
            for (int i = 0; i < 8; i++) {
                unsigned long long as2 = splat2(am[i]);
                acc[i][0] = ffma2(as2, bn0.x, acc[i][0]);
                acc[i][1] = ffma2(as2, bn0.y, acc[i][1]);
                acc[i][2] = ffma2(as2, bn1.x, acc[i][2]);
                acc[i][3] = ffma2(as2, bn1.y, acc[i][3]);
            }
        }
        cur ^= 1;
    }

    float bs[8];
#pragma unroll
    for (int j = 0; j < 8; j++) bs[j] = bias[nBase + tx * 8 + j];

#pragma unroll
    for (int i = 0; i < 8; i++) {
        int row = mBase + ty * 8 + i;
        float4 v0 = make_float4(lo2(acc[i][0]) + bs[0], hi2(acc[i][0]) + bs[1],
                                lo2(acc[i][1]) + bs[2], hi2(acc[i][1]) + bs[3]);
        float4 v1 = make_float4(lo2(acc[i][2]) + bs[4], hi2(acc[i][2]) + bs[5],
                                lo2(acc[i][3]) + bs[6], hi2(acc[i][3]) + bs[7]);
        *(float4*)&C[(size_t)row * N + nBase + tx * 8] = v0;
        *(float4*)&C[(size_t)row * N + nBase + tx * 8 + 4] = v1;
    }
}

// ---------------- persistent LSTM recurrence, dual-group, 512 threads ----------------
// 128 CTAs x 512 threads. CTA = j-tile (16 cols) x group pair (gA=bid&3, gB=gA+4).
// Thread = (kc 0..7: 64-k chunk, r 0..63: gate*16+jj). Weights: 64 floats/thread
// (32 f32x2 regs) -> no spill risk. Merged reduce+pointwise (thread owns all 4
// gates of one (jj,batch)); xg prefetched one full step ahead.
__global__ __launch_bounds__(512, 1)
void lstm_kernel(const float* __restrict__ Wh,   // [512][2048]
                 const float* __restrict__ xg,   // [B][S][2048]
                 float* __restrict__ hst) {      // [B][S][512]
    __shared__ float hsA[GB][512];
    __shared__ float hsB[GB][512];
    __shared__ float parts[8][64][GB];
    __shared__ float csm[2][16][GB];

    const int tid = threadIdx.x;
    const int bid = blockIdx.x;
    const int gA = bid & 3;
    const int gB = gA + 4;
    const int jt = bid >> 2;
    const int j0 = jt << 4;

    const int kc = tid >> 6;       // 0..7
    const int r  = tid & 63;
    const int gate = r >> 4;
    const int jj = r & 15;
    const int col = gate * 512 + j0 + jj;

    // ---- Wh slice: 64 k per thread -> 32 f32x2 regs ----
    unsigned long long w01[16], w23[16];
    {
        const float* wp = Wh + (size_t)(kc * 64) * GG + col;
#pragma unroll
        for (int i = 0; i < 16; i++) {
            float a0 = wp[0];
            float a1 = wp[GG];
            float a2 = wp[2 * GG];
            float a3 = wp[3 * GG];
            wp += 4 * GG;
            w01[i] = pack2(a0, a1);
            w23[i] = pack2(a2, a3);
        }
    }

    // pointwise-thread identity (tid < 64): owns (jjp, bbp), all 4 gates
    const int bbp = tid >> 4;      // 0..3  (valid when tid<64)
    const int jjp = tid & 15;
    const float* xbA = xg + (size_t)(gA * GB + bbp) * SS * GG + j0 + jjp;
    const float* xbB = xg + (size_t)(gB * GB + bbp) * SS * GG + j0 + jjp;

    // ---- init ----
    if (tid < 64) {
        g_hbuf[0][(gA * GB + bbp) * HH + j0 + jjp] = 0.f;
        g_hbuf[0][(gB * GB + bbp) * HH + j0 + jjp] = 0.f;
    }
    if (tid < 128) {
        int pg = tid >> 6, x = tid & 63;
        csm[pg][x & 15][x >> 4] = 0.f;
    }
    __syncthreads();
    if (tid == 0) { arrive_rel(&g_arr[gA]); arrive_rel(&g_arr[gB]); }

    // xg current-step values (prefetched one step ahead inside the loop)
    float xcA[4], xcB[4], xnA[4], xnB[4];
    if (tid < 64) {
#pragma unroll
        for (int g = 0; g < 4; g++) {
            xcA[g] = xbA[(size_t)0 * GG + g * 512];
            xcB[g] = xbB[(size_t)0 * GG + g * 512];
        }
    }

    for (int t = 0; t < SS; t++) {
        const unsigned need = 32u * (unsigned)(t + 1);
        const int pin = t & 1, pout = pin ^ 1;

        // ---- wait A, stage A h-state (one 8KB round with 512 threads) ----
        if (tid == 0) poll_ge(&g_arr[gA], need);
        __syncthreads();                       // (1) broadcast acquire
        {
            const float4* bufA4 = (const float4*)(g_hbuf[pin] + gA * GB * HH);
            float4 v = bufA4[tid];
            *(float4*)&hsA[tid >> 7][(tid & 127) * 4] = v;
        }
        __syncthreads();                       // (2)

        // prefetch next step's xg during dotA (DRAM tail off critical path)
        const int tn = (t + 1 < SS) ? (t + 1) : t;
        if (tid < 64) {
#pragma unroll
            for (int g = 0; g < 4; g++) {
                xnA[g] = xbA[(size_t)tn * GG + g * 512];
                xnB[g] = xbB[(size_t)tn * GG + g * 512];
            }
        }

        // ---- dot A ----
        unsigned long long acc[GB];
#pragma unroll
        for (int b = 0; b < GB; b++) acc[b] = 0ull;
#pragma unroll
        for (int i = 0; i < 16; i++) {
            const int kk = kc * 64 + i * 4;
#pragma unroll
            for (int b = 0; b < GB; b++) {
                ulonglong2 hv = *(const ulonglong2*)&hsA[b][kk];
                acc[b] = ffma2(w01[i], hv.x, acc[b]);
                acc[b] = ffma2(w23[i], hv.y, acc[b]);
            }
        }
        {
            float4 p;
            p.x = lo2(acc[0]) + hi2(acc[0]);
            p.y = lo2(acc[1]) + hi2(acc[1]);
            p.z = lo2(acc[2]) + hi2(acc[2]);
            p.w = lo2(acc[3]) + hi2(acc[3]);
            *(float4*)&parts[kc][r][0] = p;
        }
        if (tid == 0) poll_ge(&g_arr[gB], need);
        __syncthreads();                       // (3) partsA ready + B acquired

        // B h-state loads (latency overlaps pointwise A)
        float4 bv;
        {
            const float4* bufB4 = (const float4*)(g_hbuf[pin] + gB * GB * HH);
            bv = bufB4[tid];
        }

        // ---- merged reduce + pointwise A (64 threads own (jj,bb), 4 gates) ----
        if (tid < 64) {
            float gi = xcA[0], gf = xcA[1], gg = xcA[2], go = xcA[3];
#pragma unroll
            for (int q = 0; q < 8; q++) {
                gi += parts[q][jjp][bbp];
                gf += parts[q][16 + jjp][bbp];
                gg += parts[q][32 + jjp][bbp];
                go += parts[q][48 + jjp][bbp];
            }
            float c = fsigmoid(gf) * csm[0][jjp][bbp] + fsigmoid(gi) * ftanh(gg);
            float h = fsigmoid(go) * ftanh(c);
            csm[0][jjp][bbp] = c;
            int bglob = gA * GB + bbp;
            g_hbuf[pout][bglob * HH + j0 + jjp] = h;
            hst[((size_t)bglob * SS + t) * HH + j0 + jjp] = h;
        }
        // stage B h-state (hsB free: last step's dotB fully consumed it)
        *(float4*)&hsB[tid >> 7][(tid & 127) * 4] = bv;
        __syncthreads();                       // (4) pwA done + hsB staged
        if (tid == 0) arrive_rel(&g_arr[gA]);  // h(t+1) of A published

        // ---- dot B ----
#pragma unroll
        for (int b = 0; b < GB; b++) acc[b] = 0ull;
#pragma unroll
        for (int i = 0; i < 16; i++) {
            const int kk = kc * 64 + i * 4;
#pragma unroll
            for (int b = 0; b < GB; b++) {
                ulonglong2 hv = *(const ulonglong2*)&hsB[b][kk];
                acc[b] = ffma2(w01[i], hv.x, acc[b]);
                acc[b] = ffma2(w23[i], hv.y, acc[b]);
            }
        }
        {
            float4 p;
            p.x = lo2(acc[0]) + hi2(acc[0]);
            p.y = lo2(acc[1]) + hi2(acc[1]);
            p.z = lo2(acc[2]) + hi2(acc[2]);
            p.w = lo2(acc[3]) + hi2(acc[3]);
            *(float4*)&parts[kc][r][0] = p;
        }
        __syncthreads();                       // (5) partsB ready

        // ---- merged reduce + pointwise B ----
        if (tid < 64) {
            float gi = xcB[0], gf = xcB[1], gg = xcB[2], go = xcB[3];
#pragma unroll
            for (int q = 0; q < 8; q++) {
                gi += parts[q][jjp][bbp];
                gf += parts[q][16 + jjp][bbp];
                gg += parts[q][32 + jjp][bbp];
                go += parts[q][48 + jjp][bbp];
            }
            float c = fsigmoid(gf) * csm[1][jjp][bbp] + fsigmoid(gi) * ftanh(gg);
            float h = fsigmoid(go) * ftanh(c);
            csm[1][jjp][bbp] = c;
            int bglob = gB * GB + bbp;
            g_hbuf[pout][bglob * HH + j0 + jjp] = h;
            hst[((size_t)bglob * SS + t) * HH + j0 + jjp] = h;
            // rotate xg prefetch
#pragma unroll
            for (int g = 0; g < 4; g++) { xcA[g] = xnA[g]; xcB[g] = xnB[g]; }
        }
        __syncthreads();                       // (6) pwB done
        if (tid == 0) arrive_rel(&g_arr[gB]);  // h(t+1) of B published
    }

    // ---- reset counters for graph replay ----
    if (bid < 4 && tid == 0) {
        const unsigned total = 32u * (unsigned)(SS + 1);
        poll_ge(&g_arr[gA], total);
        poll_ge(&g_arr[gB], total);
        asm volatile("st.relaxed.gpu.global.u32 [%0], %1;" :: "l"(&g_arr[gA]), "r"(0u) : "memory");
        asm volatile("st.relaxed.gpu.global.u32 [%0], %1;" :: "l"(&g_arr[gB]), "r"(0u) : "memory");
    }
}

// ---------------- launch ----------------
extern "C" void kernel_launch(void* const* d_in, const int* in_sizes, int n_in,
                              void* d_out, int out_size) {
    const float* x  = (const float*)d_in[0];
    const float* Wx = (const float*)d_in[1];
    const float* Wh = (const float*)d_in[2];
    const float* b  = (const float*)d_in[3];
    const float* Wo = (const float*)d_in[4];
    const float* bo = (const float*)d_in[5];
    float* out = (float*)d_out;

    float *xg_p, *hst_p;
    cudaGetSymbolAddress((void**)&xg_p, g_xg);
    cudaGetSymbolAddress((void**)&hst_p, g_hst);

    // xg = x @ Wx + b   : M=65536, N=2048, K=256
    gemm_f32<<<dim3(GG / 128, (BB * SS) / 128), 256>>>(x, Wx, b, xg_p,
                                                       BB * SS, GG, DD);
    // recurrence
    lstm_kernel<<<128, 512>>>(Wh, xg_p, hst_p);
    // y = h_stacked @ Wo + bo : M=65536, N=256, K=512
    gemm_f32<<<dim3(OO / 128, (BB * SS) / 128), 256>>>(hst_p, Wo, bo, out,
                                                       BB * SS, OO, HH);
}